// round 3
// baseline (speedup 1.0000x reference)
#include <cuda_runtime.h>
#include <cuda_bf16.h>
#include <cstdint>

// Problem constants (fixed shapes from the reference setup_inputs)
#define BB    2048
#define CC    9605
#define LL    8
#define NT    256
#define TOPK  16

#define ALPHA   0.5f
#define ALPHA1  0.05f
#define ALPHA2  2.0f
#define ALPHA3  5.0f
#define ALPHA_OTHER 0.3f

// Scratch (no cudaMalloc allowed)
__device__ float         g_partial[BB];
__device__ unsigned char g_gbits[CC + 16];
__device__ int           g_maskmode;   // 0 = 4-byte elems (f32/i32), 1 = 1-byte bool

__device__ __forceinline__ float neg_inf() { return __int_as_float(0xff800000); }

__device__ __forceinline__ float sigm(float v) {
    return 1.0f / (1.0f + __expf(-v));
}

// our_rank_loss: d = x2 - x1 + margin; sigmoid(alpha3*d), doubled when violated (d>0)
__device__ __forceinline__ float rankl(float x1, float x2) {
    float d = x2 - x1 + ALPHA1;
    float s = 1.0f / (1.0f + __expf(-ALPHA3 * d));
    return d > 0.0f ? ALPHA2 * s : s;
}

// ---------------------------------------------------------------------------
// Kernel 0: classify group_mask element width from byte pattern.
//   f32 1.0 -> bytes {00,00,80,3F}: has byte > 1          -> word mode
//   i32 1   -> bytes {01,00,00,00}: ones only at off%4==0 -> word mode
//   bool    -> bytes {0,1} at arbitrary offsets           -> byte mode
// Scans exactly LL*CC bytes (in-bounds under every encoding).
// ---------------------------------------------------------------------------
__global__ void classify_mask_kernel(const unsigned char* __restrict__ m, int nbytes) {
    __shared__ int s_gt1, s_mis;
    if (threadIdx.x == 0) { s_gt1 = 0; s_mis = 0; }
    __syncthreads();
    int gt1 = 0, mis = 0;
    for (int i = threadIdx.x; i < nbytes; i += blockDim.x) {
        unsigned char v = m[i];
        if (v > 1u) gt1 = 1;
        else if (v == 1u && (i & 3)) mis = 1;
    }
    if (gt1) atomicOr(&s_gt1, 1);
    if (mis) atomicOr(&s_mis, 1);
    __syncthreads();
    if (threadIdx.x == 0) g_maskmode = (!s_gt1 && s_mis) ? 1 : 0;
}

// ---------------------------------------------------------------------------
// Kernel 1: pack per-class group membership into one byte (bit l = in group l)
// ---------------------------------------------------------------------------
__global__ void build_gbits_kernel(const unsigned char* __restrict__ mraw) {
    int c = blockIdx.x * blockDim.x + threadIdx.x;
    if (c >= CC) return;
    int mode = g_maskmode;
    unsigned int bits = 0;
    if (mode == 1) {
        #pragma unroll
        for (int l = 0; l < LL; ++l)
            if (mraw[(size_t)l * CC + c] != 0) bits |= (1u << l);
    } else {
        const unsigned int* mw = (const unsigned int*)mraw;
        #pragma unroll
        for (int l = 0; l < LL; ++l)
            if (mw[(size_t)l * CC + c] != 0u) bits |= (1u << l);  // f32 1.0 and i32 1 both nonzero
    }
    g_gbits[c] = (unsigned char)bits;
}

// ---------------------------------------------------------------------------
// Kernel 2: one CTA per sample row. Single fused streaming pass over x,y,y_neg.
// Streams are read once -> __ldcs (evict-first) to keep L2 clean.
// ---------------------------------------------------------------------------
__global__ __launch_bounds__(NT) void row_kernel(const float* __restrict__ x,
                                                 const float* __restrict__ y,
                                                 const float* __restrict__ yn) {
    __shared__ unsigned char s_gb[CC];
    __shared__ float s_top[NT * TOPK];           // 16 KB merge workspace
    __shared__ float s_gmax[NT / 32][LL];
    __shared__ float s_umax[NT / 32];
    __shared__ unsigned int s_gtb[NT / 32], s_gnb[NT / 32];

    const int b = blockIdx.x;
    const int t = threadIdx.x;
    const float* __restrict__ xr = x + (size_t)b * CC;
    const float* __restrict__ yr = y + (size_t)b * CC;
    const float* __restrict__ nr = yn + (size_t)b * CC;

    for (int i = t; i < CC; i += NT) s_gb[i] = g_gbits[i];
    __syncthreads();

    const float NI = neg_inf();
    float tk[TOPK];
    #pragma unroll
    for (int k = 0; k < TOPK; ++k) tk[k] = NI;
    float gmax[LL];
    #pragma unroll
    for (int l = 0; l < LL; ++l) gmax[l] = NI;
    float umax = NI;
    unsigned int gtb = 0, gnb = 0;

    // Fused streaming pass (raw-x domain; sigmoid applied at the end only)
    for (int i = t; i < CC; i += NT) {
        float xv = __ldcs(xr + i);
        float yv = __ldcs(yr + i);
        float nv = __ldcs(nr + i);
        unsigned int gb = s_gb[i];
        if (gb) {
            umax = fmaxf(umax, xv);
            #pragma unroll
            for (int l = 0; l < LL; ++l)
                if (gb & (1u << l)) gmax[l] = fmaxf(gmax[l], xv);
            if (yv > 0.0f) gtb |= gb;
            if (nv > 0.0f) gnb |= gb;
        }
        // local top-16 insertion (sorted descending)
        if (xv > tk[TOPK - 1]) {
            float v = xv;
            #pragma unroll
            for (int k = 0; k < TOPK; ++k) {
                if (v > tk[k]) { float tmp = tk[k]; tk[k] = v; v = tmp; }
            }
        }
    }

    // stash per-thread top-16 for the merge tree
    #pragma unroll
    for (int k = 0; k < TOPK; ++k) s_top[t * TOPK + k] = tk[k];

    // warp-level reduction of maxes / bitmasks
    const unsigned fm = 0xFFFFFFFFu;
    #pragma unroll
    for (int off = 16; off > 0; off >>= 1) {
        #pragma unroll
        for (int l = 0; l < LL; ++l)
            gmax[l] = fmaxf(gmax[l], __shfl_xor_sync(fm, gmax[l], off));
        umax = fmaxf(umax, __shfl_xor_sync(fm, umax, off));
        gtb |= __shfl_xor_sync(fm, gtb, off);
        gnb |= __shfl_xor_sync(fm, gnb, off);
    }
    const int w = t >> 5;
    if ((t & 31) == 0) {
        #pragma unroll
        for (int l = 0; l < LL; ++l) s_gmax[w][l] = gmax[l];
        s_umax[w] = umax;
        s_gtb[w] = gtb;
        s_gnb[w] = gnb;
    }
    __syncthreads();

    // pairwise merge tree: after log2(NT) levels, s_top[0..15] = global top-16
    for (int s = NT / 2; s >= 1; s >>= 1) {
        if (t < s) {
            float out[TOPK];
            const float* A  = &s_top[t * TOPK];
            const float* Bp = &s_top[(t + s) * TOPK];
            int i = 0, j = 0;
            #pragma unroll
            for (int k = 0; k < TOPK; ++k) {
                float a = A[i], c = Bp[j];
                if (a >= c) { out[k] = a; ++i; } else { out[k] = c; ++j; }
            }
            float* Aw = &s_top[t * TOPK];
            #pragma unroll
            for (int k = 0; k < TOPK; ++k) Aw[k] = out[k];
        }
        __syncthreads();
    }

    if (t == 0) {
        float gmaxA[LL];
        #pragma unroll
        for (int l = 0; l < LL; ++l) gmaxA[l] = NI;
        float umaxA = NI;
        unsigned int gtA = 0, gnA = 0;
        for (int wv = 0; wv < NT / 32; ++wv) {
            #pragma unroll
            for (int l = 0; l < LL; ++l) gmaxA[l] = fmaxf(gmaxA[l], s_gmax[wv][l]);
            umaxA = fmaxf(umaxA, s_umax[wv]);
            gtA |= s_gtb[wv];
            gnA |= s_gnb[wv];
        }

        float t16   = s_top[TOPK - 1];                 // 16th-largest raw x
        float thres = fmaxf(sigm(t16), ALPHA_OTHER);

        float loss;
        if (gtA) {
            // case B: at least one whitelist group hit
            loss = 0.0f;
            #pragma unroll
            for (int l = 0; l < LL; ++l) {
                float gm = sigm(gmaxA[l]);
                loss += ((gtA >> l) & 1u) ? rankl(gm, thres)   // gt group above thres
                                          : rankl(thres, gm);  // non-gt group below thres
            }
        } else {
            // case A
            float um   = sigm(umaxA);
            float negs = 0.0f;                         // torch starts at 0
            if (gnA) {
                float nm = NI;
                #pragma unroll
                for (int l = 0; l < LL; ++l)
                    if ((gnA >> l) & 1u) nm = fmaxf(nm, gmaxA[l]);
                negs = sigm(nm);
            }
            loss = (1.0f - ALPHA) * rankl(thres, um) + ALPHA * rankl(thres, negs);
        }
        g_partial[b] = loss;
    }
}

// ---------------------------------------------------------------------------
// Kernel 3: deterministic mean over the 2048 partials
// ---------------------------------------------------------------------------
__global__ void reduce_kernel(float* __restrict__ out) {
    __shared__ float s[256];
    float acc = 0.0f;
    for (int i = threadIdx.x; i < BB; i += 256) acc += g_partial[i];
    s[threadIdx.x] = acc;
    __syncthreads();
    for (int st = 128; st > 0; st >>= 1) {
        if (threadIdx.x < st) s[threadIdx.x] += s[threadIdx.x + st];
        __syncthreads();
    }
    if (threadIdx.x == 0) out[0] = s[0] / (float)BB;
}

extern "C" void kernel_launch(void* const* d_in, const int* in_sizes, int n_in,
                              void* d_out, int out_size) {
    (void)in_sizes; (void)n_in; (void)out_size;
    const float*         x  = (const float*)d_in[0];
    const float*         y  = (const float*)d_in[1];
    const float*         yn = (const float*)d_in[2];
    const unsigned char* m  = (const unsigned char*)d_in[3];

    classify_mask_kernel<<<1, 256>>>(m, LL * CC);
    build_gbits_kernel<<<(CC + 255) / 256, 256>>>(m);
    row_kernel<<<BB, NT>>>(x, y, yn);
    reduce_kernel<<<1, 256>>>((float*)d_out);
}

// round 4
// speedup vs baseline: 2.2710x; 2.2710x over previous
#include <cuda_runtime.h>
#include <cuda_bf16.h>
#include <cstdint>

#define BB    2048
#define CC    9605
#define LL    8
#define NT    256
#define TOPK  16
#define NBIN  64

#define ALPHA   0.5f
#define ALPHA1  0.05f
#define ALPHA2  2.0f
#define ALPHA3  5.0f
#define ALPHA_OTHER 0.3f

// Scratch (no cudaMalloc allowed)
__device__ float         g_partial[BB];
__device__ unsigned char g_gbits[CC + 16];
__device__ int           g_done;   // zero-init; reset by last block each call

__device__ __forceinline__ float sigm(float v) { return 1.0f / (1.0f + __expf(-v)); }

__device__ __forceinline__ float rankl(float x1, float x2) {
    float d = x2 - x1 + ALPHA1;
    float s = 1.0f / (1.0f + __expf(-ALPHA3 * d));
    return d > 0.0f ? ALPHA2 * s : s;
}

// monotone binning of x into 64 bins over [-4,4], clamped
__device__ __forceinline__ int binof(float x) {
    int b = (int)floorf((x + 4.0f) * 8.0f);
    return min(max(b, 0), NBIN - 1);
}

// ---------------------------------------------------------------------------
// prep: every block redundantly classifies mask dtype (byte pattern), then
// builds its slice of per-class group-membership bytes. One kernel, no
// grid-wide sync needed. Scans exactly LL*CC bytes (valid for every encoding).
//   f32 1.0 -> bytes {00,00,80,3F}: some byte has a bit above bit0 -> word mode
//   i32 1   -> ones only at offset%4==0                            -> word mode
//   bool    -> 0x01 at arbitrary offsets                           -> byte mode
// ---------------------------------------------------------------------------
__global__ void prep_kernel(const unsigned char* __restrict__ mraw) {
    __shared__ int s_gt1, s_mis;
    if (threadIdx.x == 0) { s_gt1 = 0; s_mis = 0; }
    __syncthreads();
    const unsigned int* mw = (const unsigned int*)mraw;
    unsigned int a = 0, bm = 0;
    for (int i = threadIdx.x; i < (CC * LL) / 4; i += blockDim.x) {   // 19210 words exact
        unsigned int wv = mw[i];
        a  |= (wv & 0xFEFEFEFEu);   // any byte >= 2 anywhere
        bm |= (wv & 0x01010100u);   // bit0 set in bytes at offset%4 != 0
    }
    if (a)  atomicOr(&s_gt1, 1);
    if (bm) atomicOr(&s_mis, 1);
    __syncthreads();
    const int bytemode = (!s_gt1) && s_mis;

    int c = blockIdx.x * blockDim.x + threadIdx.x;
    if (c < CC) {
        unsigned int bits = 0;
        if (bytemode) {
            #pragma unroll
            for (int l = 0; l < LL; ++l)
                if (mraw[l * CC + c] != 0) bits |= (1u << l);
        } else {
            #pragma unroll
            for (int l = 0; l < LL; ++l)
                if (mw[l * CC + c] != 0u) bits |= (1u << l);
        }
        g_gbits[c] = (unsigned char)bits;
    }
}

// ---------------------------------------------------------------------------
// row_kernel: one CTA per sample. Pass 1: fused vectorized stream of x/y/yn
// (group maxes, hit bitmasks, 64-bin histogram of x). Pass 2: re-scan x from
// L2, exact selection of 16th-largest via candidates in the critical bin.
// Tail: last CTA reduces the 2048 partials deterministically.
// ---------------------------------------------------------------------------
__global__ __launch_bounds__(NT) void row_kernel(const float* __restrict__ x,
                                                 const float* __restrict__ y,
                                                 const float* __restrict__ yn,
                                                 float* __restrict__ out) {
    __shared__ unsigned char s_gb[CC + 3];
    __shared__ int   s_hist[NT / 32][NBIN];
    __shared__ int   s_cnt[NBIN];
    __shared__ float s_top[NT * TOPK];          // merge workspace / final reduce buf
    __shared__ float s_gmax[NT / 32][LL];
    __shared__ float s_umax[NT / 32];
    __shared__ unsigned int s_gtb[NT / 32], s_gnb[NT / 32];
    __shared__ int s_beta, s_kp, s_last;

    const int b = blockIdx.x, t = threadIdx.x, w = t >> 5;
    const size_t base = (size_t)b * CC;
    const float* __restrict__ xr = x + base;
    const float* __restrict__ yr = y + base;
    const float* __restrict__ nr = yn + base;

    for (int i = t; i < CC; i += NT) s_gb[i] = g_gbits[i];
    for (int i = t; i < (NT / 32) * NBIN; i += NT) ((int*)s_hist)[i] = 0;
    __syncthreads();

    const float NI = __int_as_float(0xff800000);
    float gmax[LL];
    #pragma unroll
    for (int l = 0; l < LL; ++l) gmax[l] = NI;
    float umax = NI;
    unsigned int gtb = 0, gnb = 0;
    int* myhist = s_hist[w];

    // alignment: (b*9605) % 4 == b % 4  (9605 % 4 == 1)
    const int p  = (4 - (b & 3)) & 3;        // scalar peel count
    const int nv = (CC - p) >> 2;            // float4 count
    const int r  = (CC - p) & 3;             // scalar tail count

    // ---- pass 1: scalar peel + tail (<= 6 elements, low threads) ----
    if (t < p + r) {
        int idx = (t < p) ? t : (p + 4 * nv + (t - p));
        float xv = __ldg(xr + idx);
        atomicAdd(&myhist[binof(xv)], 1);
        unsigned int gb = s_gb[idx];
        if (gb) {
            umax = fmaxf(umax, xv);
            #pragma unroll
            for (int l = 0; l < LL; ++l)
                if (gb & (1u << l)) gmax[l] = fmaxf(gmax[l], xv);
            if (__ldg(yr + idx) > 0.0f) gtb |= gb;
            if (__ldg(nr + idx) > 0.0f) gnb |= gb;
        }
    }

    // ---- pass 1: vectorized main ----
    const float4* __restrict__ x4 = (const float4*)(xr + p);
    const float4* __restrict__ y4 = (const float4*)(yr + p);
    const float4* __restrict__ n4 = (const float4*)(nr + p);

    for (int v = t; v < nv; v += NT) {
        float4 xv = __ldg(x4 + v);                 // default policy: keep in L2 for pass 2
        int gi = p + 4 * v;
        unsigned int g0 = s_gb[gi], g1 = s_gb[gi + 1], g2 = s_gb[gi + 2], g3 = s_gb[gi + 3];
        atomicAdd(&myhist[binof(xv.x)], 1);
        atomicAdd(&myhist[binof(xv.y)], 1);
        atomicAdd(&myhist[binof(xv.z)], 1);
        atomicAdd(&myhist[binof(xv.w)], 1);
        unsigned int go = g0 | g1 | g2 | g3;
        if (go) {                                  // y/yn only needed on grouped classes
            float4 yv = __ldcs(y4 + v);            // streamed: read-once, evict-first
            float4 nvv = __ldcs(n4 + v);
            #define P1(GB, XV, YV, NV)                                              \
                if (GB) {                                                            \
                    umax = fmaxf(umax, XV);                                          \
                    _Pragma("unroll")                                                \
                    for (int l = 0; l < LL; ++l)                                     \
                        if ((GB) & (1u << l)) gmax[l] = fmaxf(gmax[l], XV);          \
                    if ((YV) > 0.0f) gtb |= (GB);                                    \
                    if ((NV) > 0.0f) gnb |= (GB);                                    \
                }
            P1(g0, xv.x, yv.x, nvv.x)
            P1(g1, xv.y, yv.y, nvv.y)
            P1(g2, xv.z, yv.z, nvv.z)
            P1(g3, xv.w, yv.w, nvv.w)
            #undef P1
        }
    }

    // warp-reduce group aggregates
    const unsigned fm = 0xFFFFFFFFu;
    #pragma unroll
    for (int off = 16; off > 0; off >>= 1) {
        #pragma unroll
        for (int l = 0; l < LL; ++l)
            gmax[l] = fmaxf(gmax[l], __shfl_xor_sync(fm, gmax[l], off));
        umax = fmaxf(umax, __shfl_xor_sync(fm, umax, off));
        gtb |= __shfl_xor_sync(fm, gtb, off);
        gnb |= __shfl_xor_sync(fm, gnb, off);
    }
    if ((t & 31) == 0) {
        #pragma unroll
        for (int l = 0; l < LL; ++l) s_gmax[w][l] = gmax[l];
        s_umax[w] = umax;
        s_gtb[w] = gtb;
        s_gnb[w] = gnb;
    }
    __syncthreads();

    // ---- histogram merge + critical-bin search ----
    if (t < NBIN) {
        int c = 0;
        #pragma unroll
        for (int j = 0; j < NT / 32; ++j) c += s_hist[j][t];
        s_cnt[t] = c;
    }
    __syncthreads();
    if (t == 0) {
        int acc = 0, beta = 0, A = 0;
        for (int j = NBIN - 1; j >= 0; --j) {
            if (acc + s_cnt[j] >= TOPK) { beta = j; A = acc; break; }
            acc += s_cnt[j];
        }
        s_beta = beta;
        s_kp = TOPK - A;          // k'-th largest inside bin beta (1-indexed), 1..16
    }
    __syncthreads();
    const int beta = s_beta, kp = s_kp;

    // ---- pass 2: candidates only (x re-read hits L2) ----
    float tk[TOPK];
    #pragma unroll
    for (int k = 0; k < TOPK; ++k) tk[k] = NI;

    #define INS(XV)                                                        \
        if (binof(XV) == beta && (XV) > tk[TOPK - 1]) {                     \
            float _v = (XV);                                               \
            _Pragma("unroll")                                              \
            for (int k = 0; k < TOPK; ++k)                                 \
                if (_v > tk[k]) { float _tmp = tk[k]; tk[k] = _v; _v = _tmp; } \
        }

    if (t < p + r) {
        int idx = (t < p) ? t : (p + 4 * nv + (t - p));
        float xv = __ldg(xr + idx);
        INS(xv)
    }
    for (int v = t; v < nv; v += NT) {
        float4 xv = __ldg(x4 + v);
        INS(xv.x) INS(xv.y) INS(xv.z) INS(xv.w)
    }
    #undef INS

    #pragma unroll
    for (int k = 0; k < TOPK; ++k) s_top[t * TOPK + k] = tk[k];
    __syncthreads();

    // merge tree over NT top-16 lists (mostly -inf; exact for any input)
    for (int s = NT / 2; s >= 1; s >>= 1) {
        if (t < s) {
            float o[TOPK];
            const float* A  = &s_top[t * TOPK];
            const float* Bp = &s_top[(t + s) * TOPK];
            int i = 0, j = 0;
            #pragma unroll
            for (int k = 0; k < TOPK; ++k) {
                float a = A[i], c = Bp[j];
                if (a >= c) { o[k] = a; ++i; } else { o[k] = c; ++j; }
            }
            float* Aw = &s_top[t * TOPK];
            #pragma unroll
            for (int k = 0; k < TOPK; ++k) Aw[k] = o[k];
        }
        __syncthreads();
    }

    // ---- per-row loss (thread 0) ----
    if (t == 0) {
        float gmaxA[LL];
        #pragma unroll
        for (int l = 0; l < LL; ++l) gmaxA[l] = NI;
        float umaxA = NI;
        unsigned int gtA = 0, gnA = 0;
        for (int wv = 0; wv < NT / 32; ++wv) {
            #pragma unroll
            for (int l = 0; l < LL; ++l) gmaxA[l] = fmaxf(gmaxA[l], s_gmax[wv][l]);
            umaxA = fmaxf(umaxA, s_umax[wv]);
            gtA |= s_gtb[wv];
            gnA |= s_gnb[wv];
        }

        float t16   = s_top[kp - 1];                 // exact 16th-largest raw x
        float thres = fmaxf(sigm(t16), ALPHA_OTHER);

        float loss;
        if (gtA) {
            loss = 0.0f;
            #pragma unroll
            for (int l = 0; l < LL; ++l) {
                float gm = sigm(gmaxA[l]);
                loss += ((gtA >> l) & 1u) ? rankl(gm, thres)
                                          : rankl(thres, gm);
            }
        } else {
            float um = sigm(umaxA);
            float negs = 0.0f;                       // torch starts at 0
            if (gnA) {
                float nm = NI;
                #pragma unroll
                for (int l = 0; l < LL; ++l)
                    if ((gnA >> l) & 1u) nm = fmaxf(nm, gmaxA[l]);
                negs = sigm(nm);
            }
            loss = (1.0f - ALPHA) * rankl(thres, um) + ALPHA * rankl(thres, negs);
        }
        g_partial[b] = loss;
    }

    // ---- fused deterministic mean: last CTA reduces all partials ----
    if (t == 0) {
        __threadfence();
        int old = atomicAdd(&g_done, 1);
        s_last = (old == BB - 1);
    }
    __syncthreads();
    if (s_last) {
        float acc = 0.0f;
        for (int i = t; i < BB; i += NT) acc += g_partial[i];   // fixed order
        s_top[t] = acc;
        __syncthreads();
        for (int st = NT / 2; st > 0; st >>= 1) {
            if (t < st) s_top[t] += s_top[t + st];
            __syncthreads();
        }
        if (t == 0) { out[0] = s_top[0] / (float)BB; g_done = 0; }
    }
}

extern "C" void kernel_launch(void* const* d_in, const int* in_sizes, int n_in,
                              void* d_out, int out_size) {
    (void)in_sizes; (void)n_in; (void)out_size;
    const float*         x  = (const float*)d_in[0];
    const float*         y  = (const float*)d_in[1];
    const float*         yn = (const float*)d_in[2];
    const unsigned char* m  = (const unsigned char*)d_in[3];

    prep_kernel<<<(CC + 1023) / 1024, 1024>>>(m);
    row_kernel<<<BB, NT>>>(x, y, yn, (float*)d_out);
}